// round 11
// baseline (speedup 1.0000x reference)
#include <cuda_runtime.h>

// ClassLoss: 1600 targets (32 batches x 50), 3 anchors, 64x64 grid, 80 classes.
// One warp per target, 16 warps per block -> 100 blocks = ONE wave on 148 SMs.
// Single launch, graph-capturable, allocation-free.
//
// Inputs (metadata order):
//   d_in[0] = output  : float32 [32,3,64,64,85]
//   d_in[1] = anchors : float32 [3,2]
//   d_in[2] = targets : float32 [32,50,5]  (cls, x, y, w, h)
// Output: float32 scalar.

#define CL_B   32
#define CL_A   3
#define CL_HW  64
#define CL_NC  80
#define CL_T   50
#define CL_NT  (CL_B * CL_T)                     // 1600 targets
#define CL_THREADS 512                           // 16 warps per block
#define CL_WPB (CL_THREADS / 32)
#define CL_BLOCKS  (CL_NT / CL_WPB)              // 100 blocks -> single wave

__device__ double       g_cl_sum  = 0.0;
__device__ double       g_cl_cnt  = 0.0;
__device__ unsigned int g_cl_done = 0u;

__global__ void __launch_bounds__(CL_THREADS)
class_loss_kernel(const float* __restrict__ output,
                  const float* __restrict__ anchors,
                  const float* __restrict__ targets,
                  float* __restrict__ out)
{
    const int lane = threadIdx.x & 31;
    const int wid  = threadIdx.x >> 5;
    const int gw   = blockIdx.x * CL_WPB + wid;   // global warp = target id

    float ce  = 0.0f;   // lane 0 only
    float msk = 0.0f;   // lane 0 only

    {
        // Targets: 5 floats, 20B. Base is 4B aligned per target; load scalar
        // but issue all 5 + anchors up-front so the LSU pipelines them.
        const float* tg = targets + (size_t)gw * 5;
        const float clsf = __ldg(tg + 0);
        const float tx   = __ldg(tg + 1);
        const float ty   = __ldg(tg + 2);
        const float tw   = __ldg(tg + 3) * (float)CL_HW;
        const float th   = __ldg(tg + 4) * (float)CL_HW;

        // IoU vs 3 anchors; strict > keeps first max, matching jnp.argmax.
        float best_iou = -1.0f;
        int   best_a   = 0;
        #pragma unroll
        for (int a = 0; a < CL_A; a++) {
            const float aw = __ldg(anchors + 2 * a);
            const float ah = __ldg(anchors + 2 * a + 1);
            const float inter = fminf(aw, tw) * fminf(ah, th);
            const float uni   = aw * ah + tw * th - inter;
            const float iou   = inter / uni;
            if (iou > best_iou) { best_iou = iou; best_a = a; }
        }

        if (best_iou > 0.5f) {
            if (lane == 0) msk = 1.0f;

            // Truncation toward zero matches .astype(int32) for positive inputs.
            int ti = (int)(tx * (float)CL_HW);
            int tj = (int)(ty * (float)CL_HW);
            ti = ti < 0 ? 0 : (ti > CL_HW - 1 ? CL_HW - 1 : ti);
            tj = tj < 0 ? 0 : (tj > CL_HW - 1 ? CL_HW - 1 : tj);

            const float* row = output
                + ((((size_t)gw / CL_T * CL_A + best_a) * CL_HW + tj) * CL_HW + ti)
                  * (5 + CL_NC) + 5;

            // 80 logits: lanes cover [lane], [lane+32], lane<16 also [lane+64].
            const float x0 = __ldg(row + lane);
            const float x1 = __ldg(row + lane + 32);
            const float x2 = (lane < 16) ? __ldg(row + lane + 64) : -3.402823466e38f;

            // warp max
            float m = fmaxf(fmaxf(x0, x1), x2);
            #pragma unroll
            for (int o = 16; o; o >>= 1)
                m = fmaxf(m, __shfl_xor_sync(0xffffffffu, m, o));

            // warp sum of exp(x - m)  (MUFU exp: plenty of accuracy headroom)
            float s = __expf(x0 - m) + __expf(x1 - m);
            if (lane < 16) s += __expf(x2 - m);
            #pragma unroll
            for (int o = 16; o; o >>= 1)
                s += __shfl_xor_sync(0xffffffffu, s, o);

            if (lane == 0) {
                const int cls = (int)clsf;
                const float xc = __ldg(row + cls);
                ce = m + logf(s) - xc;   // = -(log_softmax[cls])
            }
        }
    }

    // Block reduction (16 warps), then one pair of double atomics per block.
    __shared__ float s_ce[CL_WPB];
    __shared__ float s_mk[CL_WPB];
    if (lane == 0) { s_ce[wid] = ce; s_mk[wid] = msk; }
    __syncthreads();

    if (threadIdx.x == 0) {
        float bs = 0.0f, bm = 0.0f;
        #pragma unroll
        for (int i = 0; i < CL_WPB; i++) { bs += s_ce[i]; bm += s_mk[i]; }
        if (bm != 0.0f) {
            atomicAdd(&g_cl_sum, (double)bs);
            atomicAdd(&g_cl_cnt, (double)bm);
        }
        __threadfence();
        const unsigned int d = atomicAdd(&g_cl_done, 1u);
        if (d == (unsigned int)(gridDim.x - 1)) {
            // Last block: coherent read via atomic, write result, reset state
            // so every graph replay starts from zeros.
            const double S = atomicAdd(&g_cl_sum, 0.0);
            const double C = atomicAdd(&g_cl_cnt, 0.0);
            out[0] = (C > 0.0) ? (float)(S / C) : 0.0f;
            atomicExch((unsigned long long*)&g_cl_sum, 0ull);
            atomicExch((unsigned long long*)&g_cl_cnt, 0ull);
            atomicExch(&g_cl_done, 0u);
        }
    }
}

extern "C" void kernel_launch(void* const* d_in, const int* in_sizes, int n_in,
                              void* d_out, int out_size)
{
    (void)in_sizes; (void)n_in; (void)out_size;
    const float* output  = (const float*)d_in[0];
    const float* anchors = (const float*)d_in[1];
    const float* targets = (const float*)d_in[2];
    float* out = (float*)d_out;

    class_loss_kernel<<<CL_BLOCKS, CL_THREADS>>>(output, anchors, targets, out);
}

// round 13
// speedup vs baseline: 1.0294x; 1.0294x over previous
#include <cuda_runtime.h>

// ClassLoss: 1600 targets (32 batches x 50), 3 anchors, 64x64 grid, 80 classes.
// One warp per target, 16 warps per block -> 100 blocks = ONE wave on 148 SMs.
// Single launch, graph-capturable, allocation-free.
//
// Inputs (metadata order):
//   d_in[0] = output  : float32 [32,3,64,64,85]
//   d_in[1] = anchors : float32 [3,2]
//   d_in[2] = targets : float32 [32,50,5]  (cls, x, y, w, h)
// Output: float32 scalar.

#define CL_B   32
#define CL_A   3
#define CL_HW  64
#define CL_NC  80
#define CL_T   50
#define CL_NT  (CL_B * CL_T)                     // 1600 targets
#define CL_THREADS 512                           // 16 warps per block
#define CL_WPB (CL_THREADS / 32)
#define CL_BLOCKS  (CL_NT / CL_WPB)              // 100 blocks -> single wave

__device__ double       g_cl_sum  = 0.0;
__device__ double       g_cl_cnt  = 0.0;
__device__ unsigned int g_cl_done = 0u;

__global__ void __launch_bounds__(CL_THREADS)
class_loss_kernel(const float* __restrict__ output,
                  const float* __restrict__ anchors,
                  const float* __restrict__ targets,
                  float* __restrict__ out)
{
    const int lane = threadIdx.x & 31;
    const int wid  = threadIdx.x >> 5;
    const int gw   = blockIdx.x * CL_WPB + wid;   // global warp = target id

    float ce  = 0.0f;   // lane 0 only
    float msk = 0.0f;   // lane 0 only

    {
        // Targets: 5 floats, 20B. Base is 4B aligned per target; load scalar
        // but issue all 5 + anchors up-front so the LSU pipelines them.
        const float* tg = targets + (size_t)gw * 5;
        const float clsf = __ldg(tg + 0);
        const float tx   = __ldg(tg + 1);
        const float ty   = __ldg(tg + 2);
        const float tw   = __ldg(tg + 3) * (float)CL_HW;
        const float th   = __ldg(tg + 4) * (float)CL_HW;

        // IoU vs 3 anchors; strict > keeps first max, matching jnp.argmax.
        float best_iou = -1.0f;
        int   best_a   = 0;
        #pragma unroll
        for (int a = 0; a < CL_A; a++) {
            const float aw = __ldg(anchors + 2 * a);
            const float ah = __ldg(anchors + 2 * a + 1);
            const float inter = fminf(aw, tw) * fminf(ah, th);
            const float uni   = aw * ah + tw * th - inter;
            const float iou   = inter / uni;
            if (iou > best_iou) { best_iou = iou; best_a = a; }
        }

        if (best_iou > 0.5f) {
            if (lane == 0) msk = 1.0f;

            // Truncation toward zero matches .astype(int32) for positive inputs.
            int ti = (int)(tx * (float)CL_HW);
            int tj = (int)(ty * (float)CL_HW);
            ti = ti < 0 ? 0 : (ti > CL_HW - 1 ? CL_HW - 1 : ti);
            tj = tj < 0 ? 0 : (tj > CL_HW - 1 ? CL_HW - 1 : tj);

            const float* row = output
                + ((((size_t)gw / CL_T * CL_A + best_a) * CL_HW + tj) * CL_HW + ti)
                  * (5 + CL_NC) + 5;

            // 80 logits: lanes cover [lane], [lane+32], lane<16 also [lane+64].
            const float x0 = __ldg(row + lane);
            const float x1 = __ldg(row + lane + 32);
            const float x2 = (lane < 16) ? __ldg(row + lane + 64) : -3.402823466e38f;

            // warp max
            float m = fmaxf(fmaxf(x0, x1), x2);
            #pragma unroll
            for (int o = 16; o; o >>= 1)
                m = fmaxf(m, __shfl_xor_sync(0xffffffffu, m, o));

            // warp sum of exp(x - m)  (MUFU exp: plenty of accuracy headroom)
            float s = __expf(x0 - m) + __expf(x1 - m);
            if (lane < 16) s += __expf(x2 - m);
            #pragma unroll
            for (int o = 16; o; o >>= 1)
                s += __shfl_xor_sync(0xffffffffu, s, o);

            if (lane == 0) {
                const int cls = (int)clsf;
                const float xc = __ldg(row + cls);
                ce = m + logf(s) - xc;   // = -(log_softmax[cls])
            }
        }
    }

    // Block reduction (16 warps), then one pair of double atomics per block.
    __shared__ float s_ce[CL_WPB];
    __shared__ float s_mk[CL_WPB];
    if (lane == 0) { s_ce[wid] = ce; s_mk[wid] = msk; }
    __syncthreads();

    if (threadIdx.x == 0) {
        float bs = 0.0f, bm = 0.0f;
        #pragma unroll
        for (int i = 0; i < CL_WPB; i++) { bs += s_ce[i]; bm += s_mk[i]; }
        if (bm != 0.0f) {
            atomicAdd(&g_cl_sum, (double)bs);
            atomicAdd(&g_cl_cnt, (double)bm);
        }
        __threadfence();
        const unsigned int d = atomicAdd(&g_cl_done, 1u);
        if (d == (unsigned int)(gridDim.x - 1)) {
            // Last block: coherent read via atomic, write result, reset state
            // so every graph replay starts from zeros.
            const double S = atomicAdd(&g_cl_sum, 0.0);
            const double C = atomicAdd(&g_cl_cnt, 0.0);
            out[0] = (C > 0.0) ? (float)(S / C) : 0.0f;
            atomicExch((unsigned long long*)&g_cl_sum, 0ull);
            atomicExch((unsigned long long*)&g_cl_cnt, 0ull);
            atomicExch(&g_cl_done, 0u);
        }
    }
}

extern "C" void kernel_launch(void* const* d_in, const int* in_sizes, int n_in,
                              void* d_out, int out_size)
{
    (void)in_sizes; (void)n_in; (void)out_size;
    const float* output  = (const float*)d_in[0];
    const float* anchors = (const float*)d_in[1];
    const float* targets = (const float*)d_in[2];
    float* out = (float*)d_out;

    class_loss_kernel<<<CL_BLOCKS, CL_THREADS>>>(output, anchors, targets, out);
}

// round 14
// speedup vs baseline: 1.0332x; 1.0037x over previous
#include <cuda_runtime.h>

// ClassLoss: 1600 targets (32 batches x 50), 3 anchors, 64x64 grid, 80 classes.
// One warp per target, 16 warps per block -> 100 blocks = ONE wave on 148 SMs.
// Single launch, graph-capturable, allocation-free.
//
// Inputs (metadata order):
//   d_in[0] = output  : float32 [32,3,64,64,85]
//   d_in[1] = anchors : float32 [3,2]
//   d_in[2] = targets : float32 [32,50,5]  (cls, x, y, w, h)
// Output: float32 scalar.

#define CL_B   32
#define CL_A   3
#define CL_HW  64
#define CL_NC  80
#define CL_T   50
#define CL_NT  (CL_B * CL_T)                     // 1600 targets
#define CL_THREADS 512                           // 16 warps per block
#define CL_WPB (CL_THREADS / 32)
#define CL_BLOCKS  (CL_NT / CL_WPB)              // 100 blocks -> single wave

__device__ double       g_cl_sum  = 0.0;
__device__ double       g_cl_cnt  = 0.0;
__device__ unsigned int g_cl_done = 0u;

__global__ void __launch_bounds__(CL_THREADS)
class_loss_kernel(const float* __restrict__ output,
                  const float* __restrict__ anchors,
                  const float* __restrict__ targets,
                  float* __restrict__ out)
{
    const int lane = threadIdx.x & 31;
    const int wid  = threadIdx.x >> 5;
    const int gw   = blockIdx.x * CL_WPB + wid;   // global warp = target id

    float ce  = 0.0f;   // lane 0 only
    float msk = 0.0f;   // lane 0 only

    {
        // Targets: 5 floats, 20B. Base is 4B aligned per target; load scalar
        // but issue all 5 + anchors up-front so the LSU pipelines them.
        const float* tg = targets + (size_t)gw * 5;
        const float clsf = __ldg(tg + 0);
        const float tx   = __ldg(tg + 1);
        const float ty   = __ldg(tg + 2);
        const float tw   = __ldg(tg + 3) * (float)CL_HW;
        const float th   = __ldg(tg + 4) * (float)CL_HW;

        // IoU vs 3 anchors; strict > keeps first max, matching jnp.argmax.
        float best_iou = -1.0f;
        int   best_a   = 0;
        #pragma unroll
        for (int a = 0; a < CL_A; a++) {
            const float aw = __ldg(anchors + 2 * a);
            const float ah = __ldg(anchors + 2 * a + 1);
            const float inter = fminf(aw, tw) * fminf(ah, th);
            const float uni   = aw * ah + tw * th - inter;
            const float iou   = inter / uni;
            if (iou > best_iou) { best_iou = iou; best_a = a; }
        }

        if (best_iou > 0.5f) {
            if (lane == 0) msk = 1.0f;

            // Truncation toward zero matches .astype(int32) for positive inputs.
            int ti = (int)(tx * (float)CL_HW);
            int tj = (int)(ty * (float)CL_HW);
            ti = ti < 0 ? 0 : (ti > CL_HW - 1 ? CL_HW - 1 : ti);
            tj = tj < 0 ? 0 : (tj > CL_HW - 1 ? CL_HW - 1 : tj);

            const float* row = output
                + ((((size_t)gw / CL_T * CL_A + best_a) * CL_HW + tj) * CL_HW + ti)
                  * (5 + CL_NC) + 5;

            // 80 logits: lanes cover [lane], [lane+32], lane<16 also [lane+64].
            const float x0 = __ldg(row + lane);
            const float x1 = __ldg(row + lane + 32);
            const float x2 = (lane < 16) ? __ldg(row + lane + 64) : -3.402823466e38f;

            // warp max
            float m = fmaxf(fmaxf(x0, x1), x2);
            #pragma unroll
            for (int o = 16; o; o >>= 1)
                m = fmaxf(m, __shfl_xor_sync(0xffffffffu, m, o));

            // warp sum of exp(x - m)  (MUFU exp: plenty of accuracy headroom)
            float s = __expf(x0 - m) + __expf(x1 - m);
            if (lane < 16) s += __expf(x2 - m);
            #pragma unroll
            for (int o = 16; o; o >>= 1)
                s += __shfl_xor_sync(0xffffffffu, s, o);

            if (lane == 0) {
                const int cls = (int)clsf;
                const float xc = __ldg(row + cls);
                ce = m + logf(s) - xc;   // = -(log_softmax[cls])
            }
        }
    }

    // Block reduction (16 warps), then one pair of double atomics per block.
    __shared__ float s_ce[CL_WPB];
    __shared__ float s_mk[CL_WPB];
    if (lane == 0) { s_ce[wid] = ce; s_mk[wid] = msk; }
    __syncthreads();

    if (threadIdx.x == 0) {
        float bs = 0.0f, bm = 0.0f;
        #pragma unroll
        for (int i = 0; i < CL_WPB; i++) { bs += s_ce[i]; bm += s_mk[i]; }
        if (bm != 0.0f) {
            atomicAdd(&g_cl_sum, (double)bs);
            atomicAdd(&g_cl_cnt, (double)bm);
        }
        __threadfence();
        const unsigned int d = atomicAdd(&g_cl_done, 1u);
        if (d == (unsigned int)(gridDim.x - 1)) {
            // Last block: coherent read via atomic, write result, reset state
            // so every graph replay starts from zeros.
            const double S = atomicAdd(&g_cl_sum, 0.0);
            const double C = atomicAdd(&g_cl_cnt, 0.0);
            out[0] = (C > 0.0) ? (float)(S / C) : 0.0f;
            atomicExch((unsigned long long*)&g_cl_sum, 0ull);
            atomicExch((unsigned long long*)&g_cl_cnt, 0ull);
            atomicExch(&g_cl_done, 0u);
        }
    }
}

extern "C" void kernel_launch(void* const* d_in, const int* in_sizes, int n_in,
                              void* d_out, int out_size)
{
    (void)in_sizes; (void)n_in; (void)out_size;
    const float* output  = (const float*)d_in[0];
    const float* anchors = (const float*)d_in[1];
    const float* targets = (const float*)d_in[2];
    float* out = (float*)d_out;

    class_loss_kernel<<<CL_BLOCKS, CL_THREADS>>>(output, anchors, targets, out);
}